// round 10
// baseline (speedup 1.0000x reference)
#include <cuda_runtime.h>

#define L_SEQ 96
#define N_V   207
#define N_B   4
#define N_C   512          // H*E channels
#define TOPK  4
#define CHUNK_C 32         // channels per smem chunk (16 float2 pairs)
#define TPB_A 128          // 2 t-halves * 4 lag-groups * 16 channel-pairs
#define JL    24           // lags per thread (24 FFMA2 per 2 LDS.64 -> fma-dominant)
#define HC_CHUNKS 8        // chunks per channel-half (8*32 = 256 channels)

// scratch (device globals: no allocation allowed)
__device__ float g_mv2[N_B * N_V * 2 * L_SEQ]; // partial corr sums per channel-half
__device__ int   g_idx[N_V * TOPK];
__device__ float g_prob[N_B * N_V * TOPK];

// Packed fp32x2 FMA (Blackwell FFMA2) — 2x fp32 MAC throughput
__device__ __forceinline__ unsigned long long ffma2(unsigned long long a,
                                                    unsigned long long b,
                                                    unsigned long long c) {
    unsigned long long d;
    asm("fma.rn.f32x2 %0, %1, %2, %3;" : "=l"(d) : "l"(a), "l"(b), "l"(c));
    return d;
}

__device__ __forceinline__ void cp16(unsigned dst, const void* src) {
    asm volatile("cp.async.ca.shared.global [%0], [%1], 16;" :: "r"(dst), "l"(src));
}
__device__ __forceinline__ void cp_commit() {
    asm volatile("cp.async.commit_group;");
}
__device__ __forceinline__ void cp_wait0() {
    asm volatile("cp.async.wait_group 0;");
}

// ---------------------------------------------------------------------------
// Phase A: mean correlation partial sums.
// One CTA per (b, v, channel-half). Thread (t-half, lg, cp) owns lags
// [24*lg, 24*lg+23] on channel pair cp, summing t over its 48-step half.
// 24 FFMA2 per 2 LDS.64 -> 86% fma instruction mix.
// DOUBLE-BUFFERED staging: while computing chunk c from buffer c&1, the CTA
// issues cp.async for chunk c+1 into the other buffer. Staging latency is
// hidden behind the ~600-cycle compute phase instead of being a serialized
// stage->sync->compute sequence. smem 74.5KB -> 3 CTAs/SM; grid 1656 ->
// 3.73 waves (~93% wave efficiency, unchanged from R8).
// k staged duplicated (k2[i]=k[i%96], linear addressing); rolling 24-reg
// window; each buffer has an explicit pad row for the t=96 / row-192
// prefetch overruns.
// ---------------------------------------------------------------------------
#define SQ_N   (L_SEQ * 16 + 16)        // 96 rows + 1 pad row (u64 units)
#define SK2_N  (2 * L_SEQ * 16 + 16)    // 192 rows + 1 pad row

__global__ __launch_bounds__(TPB_A, 3) void corr_kernel(const float* __restrict__ q,
                                                        const float* __restrict__ k) {
    __shared__ unsigned long long sq [2][SQ_N];
    __shared__ unsigned long long sk2[2][SK2_N];

    const int tid  = threadIdx.x;
    const int unit = blockIdx.x;        // (b*N_V + v)*2 + hc
    const int bv   = unit >> 1;
    const int hc   = unit & 1;
    const int b = bv / N_V, v = bv % N_V;
    const int cp   = tid & 15;          // channel pair in chunk
    const int lg   = (tid >> 4) & 3;    // lag group 0..3
    const int half = tid >> 6;          // t-half 0..1
    const int t0   = half * 48;
    const int base = L_SEQ - JL * lg;   // k2[t+base-j] = k[(t-(24lg+j))%96]

    unsigned long long acc[JL];
#pragma unroll
    for (int j = 0; j < JL; ++j) acc[j] = 0ull;

    const size_t row0 = ((size_t)b * L_SEQ * N_V + v) * N_C;
    const size_t rstr = (size_t)N_V * N_C;

    const unsigned sq_s0  = (unsigned)__cvta_generic_to_shared(&sq[0][0]);
    const unsigned sq_s1  = (unsigned)__cvta_generic_to_shared(&sq[1][0]);
    const unsigned sk_s0  = (unsigned)__cvta_generic_to_shared(&sk2[0][0]);
    const unsigned sk_s1  = (unsigned)__cvta_generic_to_shared(&sk2[1][0]);

    // stage chunk ch into buffer buf (all async; caller commits)
    auto stage = [&](int ch, int buf) {
        const int c0 = ch * CHUNK_C;
        const unsigned sqb = buf ? sq_s1 : sq_s0;
        const unsigned skb = buf ? sk_s1 : sk_s0;
#pragma unroll
        for (int it = 0; it < 768 / TPB_A; ++it) {
            const int i = tid + it * TPB_A;
            const int t = i >> 3, f = i & 7;
            const size_t off = row0 + (size_t)t * rstr + c0 + 4 * f;
            const unsigned so = (unsigned)((t * 16 + 2 * f) * 8);
            cp16(sqb + so, q + off);
            cp16(skb + so, k + off);
            cp16(skb + so + (unsigned)(L_SEQ * 16 * 8), k + off);
        }
    };

    stage(hc * HC_CHUNKS, 0);
    cp_commit();

    for (int c = 0; c < HC_CHUNKS; ++c) {
        const int buf = c & 1;
        cp_wait0();
        __syncthreads();                     // buffer `buf` fully staged, all
                                             // threads past previous compute
        if (c + 1 < HC_CHUNKS) {
            stage(hc * HC_CHUNKS + c + 1, buf ^ 1);
            cp_commit();
        }

        // rolling window: slot s preloaded with k2[t0+base-24+s] for s=1..23
        unsigned long long w[JL];
#pragma unroll
        for (int s = 1; s < JL; ++s) w[s] = sk2[buf][(t0 + base - JL + s) * 16 + cp];
        const unsigned long long* kp = &sk2[buf][base * 16 + cp];
        const unsigned long long* qp = &sq[buf][cp];

        unsigned long long kv_n = kp[t0 * 16];
        unsigned long long qv_n = qp[t0 * 16];
#pragma unroll
        for (int tb = 0; tb < 48; tb += JL) {
#pragma unroll
            for (int p = 0; p < JL; ++p) {
                const int t = t0 + tb + p;
                const unsigned long long qv = qv_n;
                w[p] = kv_n;                               // k2[t+base]
                kv_n = kp[(t + 1) * 16];                   // row <=192 -> pad row
                qv_n = qp[(t + 1) * 16];                   // row 96 -> pad row
#pragma unroll
                for (int j = 0; j < JL; ++j)
                    acc[j] = ffma2(qv, w[(p - j + JL) % JL], acc[j]);  // lag 24lg+j
            }
        }
        __syncthreads();
    }

    // reduce across 16 channel pairs x 2 halves; reuse sq[0] as scratch
    float* red = reinterpret_cast<float*>(&sq[0][0]);
#pragma unroll
    for (int j = 0; j < JL; ++j) {
        const float lo = __uint_as_float((unsigned)(acc[j] & 0xffffffffull));
        const float hi = __uint_as_float((unsigned)(acc[j] >> 32));
        red[(lg * JL + j) * 32 + half * 16 + cp] = lo + hi;
    }
    __syncthreads();
    if (tid < L_SEQ) {
        float s = 0.f;
#pragma unroll
        for (int i = 0; i < 32; ++i) s += red[tid * 32 + i];
        g_mv2[(size_t)unit * L_SEQ + tid] = s;
    }
}

// ---------------------------------------------------------------------------
// Phase B: combine channel-halves, global mean over b, top-4 per v (ties ->
// lowest index, matching lax.top_k), softmax per (b,v). Tiny.
// ---------------------------------------------------------------------------
__global__ void topk_kernel() {
    const int v = blockIdx.x;
    __shared__ float gm[L_SEQ];
    __shared__ int ids[TOPK];
    const int tid = threadIdx.x;
    if (tid < L_SEQ) {
        float s = 0.f;
        for (int b = 0; b < N_B; ++b) {
            const int u = (b * N_V + v) * 2;
            s += g_mv2[(size_t)u * L_SEQ + tid] + g_mv2[(size_t)(u + 1) * L_SEQ + tid];
        }
        gm[tid] = s;
    }
    __syncthreads();
    if (tid == 0) {
        for (int kk = 0; kk < TOPK; ++kk) {
            float best = -3.0e38f; int bi = 0;
            for (int l = 0; l < L_SEQ; ++l)
                if (gm[l] > best) { best = gm[l]; bi = l; }
            ids[kk] = bi;
            gm[bi] = -3.0e38f;
            g_idx[v * TOPK + kk] = bi;
        }
    }
    __syncthreads();
    if (tid < N_B) {
        const int b = tid;
        const int u = (b * N_V + v) * 2;
        float w[TOPK];
        float mx = -3.0e38f;
        for (int kk = 0; kk < TOPK; ++kk) {
            const int id = ids[kk];
            w[kk] = (g_mv2[(size_t)u * L_SEQ + id] + g_mv2[(size_t)(u + 1) * L_SEQ + id])
                    * (1.0f / 512.0f);
            mx = fmaxf(mx, w[kk]);
        }
        float se = 0.f;
        for (int kk = 0; kk < TOPK; ++kk) { w[kk] = expf(w[kk] - mx); se += w[kk]; }
        const float inv = 1.0f / se;
        for (int kk = 0; kk < TOPK; ++kk)
            g_prob[(b * N_V + v) * TOPK + kk] = w[kk] * inv;
    }
}

// ---------------------------------------------------------------------------
// Phase C: out[b,l,v,e,h] = sum_kk p * val[b,(l+idx_kk)%96,v,h,e].
// Read-once, one CTA per (b, v, e-octant). The (h,e)->(e,h) transpose happens
// DURING staging: smem is output-major s[t*64 + co] with co = e'*8+h, so the
// compute pass is pure LDS.128 + FFMA + STG.128, all conflict-free/coalesced.
// ---------------------------------------------------------------------------
#define TPB_G 256

__global__ __launch_bounds__(TPB_G) void agg_kernel(const float* __restrict__ val,
                                                    float* __restrict__ out) {
    __shared__ float s[L_SEQ * 64];            // 24,576 B, output-major
    const int blk = blockIdx.x;
    const int bv = blk >> 3;
    const int ep = blk & 7;                    // e-octant
    const int b = bv / N_V, v = bv % N_V;
    const int e0 = ep * 8;
    const int tid = threadIdx.x;

    int idx[TOPK]; float p[TOPK];
#pragma unroll
    for (int kk = 0; kk < TOPK; ++kk) {
        idx[kk] = g_idx[v * TOPK + kk];
        p[kk]   = g_prob[(b * N_V + v) * TOPK + kk];
    }
    const size_t base = ((size_t)b * L_SEQ * N_V + v) * N_C;
    const size_t rstr = (size_t)N_V * N_C;

    // stage + transpose: 96 t x 8 h x 8 e' floats as 3072 float2 loads
#pragma unroll
    for (int it = 0; it < 3072 / TPB_G; ++it) {
        const int j = tid + it * TPB_G;
        const int t = j >> 5;
        const int r = j & 31;
        const int h = r >> 2;
        const int e2 = (r & 3) * 2;
        const float2 x = *reinterpret_cast<const float2*>(
            val + base + (size_t)t * rstr + h * 64 + e0 + e2);
        s[t * 64 + e2 * 8 + h]       = x.x;     // co = e'*8 + h
        s[t * 64 + (e2 + 1) * 8 + h] = x.y;
    }
    __syncthreads();

    const int co0 = (tid & 15) * 4;  // 4 consecutive out channels
    const int lz  = tid >> 4;        // 0..15

#pragma unroll
    for (int li = 0; li < L_SEQ / 16; ++li) {
        const int l = lz + li * 16;
        float4 r = make_float4(0.f, 0.f, 0.f, 0.f);
#pragma unroll
        for (int kk = 0; kk < TOPK; ++kk) {
            int t = l + idx[kk];
            if (t >= L_SEQ) t -= L_SEQ;
            const float4 x = *reinterpret_cast<const float4*>(&s[t * 64 + co0]);
            r.x += p[kk] * x.x; r.y += p[kk] * x.y;
            r.z += p[kk] * x.z; r.w += p[kk] * x.w;
        }
        *reinterpret_cast<float4*>(out + base + (size_t)l * rstr + e0 * 8 + co0) = r;
    }
}

extern "C" void kernel_launch(void* const* d_in, const int* in_sizes, int n_in,
                              void* d_out, int out_size) {
    const float* q  = (const float*)d_in[0];
    const float* k  = (const float*)d_in[1];
    const float* vv = (const float*)d_in[2];
    float* out = (float*)d_out;

    corr_kernel<<<N_B * N_V * 2, TPB_A>>>(q, k);
    topk_kernel<<<N_V, 128>>>();
    agg_kernel<<<N_B * N_V * 8, TPB_G>>>(vv, out);
}

// round 12
// speedup vs baseline: 1.1155x; 1.1155x over previous
#include <cuda_runtime.h>

#define L_SEQ 96
#define N_V   207
#define N_B   4
#define N_C   512          // H*E channels
#define TOPK  4
#define CHUNK_C 32         // channels per smem chunk (16 float2 pairs)
#define TPB_A 128          // 2 t-halves * 4 lag-groups * 16 channel-pairs
#define JL    24           // lags per thread (24 FFMA2 per 2 LDS.64 -> fma-dominant)
#define HC_CHUNKS 4        // chunks per work unit (4*32 = 128 channels)
#define N_UNITS 4          // channel quarters per (b,v)

// scratch (device globals: no allocation allowed)
__device__ float g_mv4[N_B * N_V * N_UNITS * L_SEQ]; // partial corr sums per quarter
__device__ int   g_idx[N_V * TOPK];
__device__ float g_prob[N_B * N_V * TOPK];

// Packed fp32x2 FMA (Blackwell FFMA2) — 2x fp32 MAC throughput
__device__ __forceinline__ unsigned long long ffma2(unsigned long long a,
                                                    unsigned long long b,
                                                    unsigned long long c) {
    unsigned long long d;
    asm("fma.rn.f32x2 %0, %1, %2, %3;" : "=l"(d) : "l"(a), "l"(b), "l"(c));
    return d;
}

// ---------------------------------------------------------------------------
// Phase A: mean correlation partial sums.
// One CTA per (b, v, channel-quarter): 3312 CTAs. At 4 CTAs/SM (592 slots)
// that is 5.59 waves -> ~96% discrete-wave efficiency with work-steal
// smoothing (vs 93% at the R9 half-split), and the per-CTA cold-start stage
// shrinks to 1/4 of chunks.
// Thread (t-half, lg, cp) owns lags [24*lg, 24*lg+23] on channel pair cp,
// summing t over its 48-step half. 24 FFMA2 per 2 LDS.64 -> 86% fma mix.
// k staged duplicated (k2[i]=k[i%96], linear addressing); rolling 24-reg
// window. Inner loop identical to the validated R9 kernel.
// ---------------------------------------------------------------------------
#define SQ_N   (L_SEQ * 16 + 16)        // +1 row pad for q prefetch overrun
#define SK2_N  (2 * L_SEQ * 16)

__global__ __launch_bounds__(TPB_A, 4) void corr_kernel(const float* __restrict__ q,
                                                        const float* __restrict__ k) {
    __shared__ unsigned long long sq [SQ_N];
    __shared__ unsigned long long sk2[SK2_N];

    const int tid  = threadIdx.x;
    const int unit = blockIdx.x;        // (b*N_V + v)*4 + hc
    const int bv   = unit >> 2;
    const int hc   = unit & 3;
    const int b = bv / N_V, v = bv % N_V;
    const int cp   = tid & 15;          // channel pair in chunk
    const int lg   = (tid >> 4) & 3;    // lag group 0..3
    const int half = tid >> 6;          // t-half 0..1
    const int t0   = half * 48;
    const int base = L_SEQ - JL * lg;   // k2[t+base-j] = k[(t-(24lg+j))%96]

    unsigned long long acc[JL];
#pragma unroll
    for (int j = 0; j < JL; ++j) acc[j] = 0ull;

    const size_t row0 = ((size_t)b * L_SEQ * N_V + v) * N_C;
    const size_t rstr = (size_t)N_V * N_C;

    for (int ch = hc * HC_CHUNKS; ch < (hc + 1) * HC_CHUNKS; ++ch) {
        const int c0 = ch * CHUNK_C;
        // stage: 96 rows x 8 float4 per row = 768 float4 loads each for q,k
#pragma unroll
        for (int it = 0; it < 768 / TPB_A; ++it) {
            const int i = tid + it * TPB_A;
            const int t = i >> 3, f = i & 7;
            const size_t off = row0 + (size_t)t * rstr + c0 + 4 * f;
            const float4 qv = *reinterpret_cast<const float4*>(q + off);
            const float4 kv = *reinterpret_cast<const float4*>(k + off);
            const unsigned long long* qu = reinterpret_cast<const unsigned long long*>(&qv);
            const unsigned long long* ku = reinterpret_cast<const unsigned long long*>(&kv);
            sq[t * 16 + 2 * f]     = qu[0];
            sq[t * 16 + 2 * f + 1] = qu[1];
            sk2[t * 16 + 2 * f]     = ku[0];
            sk2[t * 16 + 2 * f + 1] = ku[1];
            sk2[(t + L_SEQ) * 16 + 2 * f]     = ku[0];
            sk2[(t + L_SEQ) * 16 + 2 * f + 1] = ku[1];
        }
        __syncthreads();

        // rolling window: slot s preloaded with k2[t0+base-24+s] for s=1..23
        unsigned long long w[JL];
#pragma unroll
        for (int s = 1; s < JL; ++s) w[s] = sk2[(t0 + base - JL + s) * 16 + cp];
        const unsigned long long* kp = sk2 + base * 16 + cp;
        const unsigned long long* qp = sq + cp;

        unsigned long long kv_n = kp[t0 * 16];
        unsigned long long qv_n = qp[t0 * 16];
#pragma unroll
        for (int tb = 0; tb < 48; tb += JL) {
#pragma unroll
            for (int p = 0; p < JL; ++p) {
                const int t = t0 + tb + p;
                const unsigned long long qv = qv_n;
                w[p] = kv_n;                               // k2[t+base]
                kv_n = kp[(t + 1) * 16];                   // max idx < 192 rows
                qv_n = qp[(t + 1) * 16];                   // hits pad row at t=96
#pragma unroll
                for (int j = 0; j < JL; ++j)
                    acc[j] = ffma2(qv, w[(p - j + JL) % JL], acc[j]);  // lag 24lg+j
            }
        }
        __syncthreads();
    }

    // reduce across 16 channel pairs x 2 halves; reuse sq storage as scratch
    float* red = reinterpret_cast<float*>(sq);
#pragma unroll
    for (int j = 0; j < JL; ++j) {
        const float lo = __uint_as_float((unsigned)(acc[j] & 0xffffffffull));
        const float hi = __uint_as_float((unsigned)(acc[j] >> 32));
        red[(lg * JL + j) * 32 + half * 16 + cp] = lo + hi;
    }
    __syncthreads();
    if (tid < L_SEQ) {
        float s = 0.f;
#pragma unroll
        for (int i = 0; i < 32; ++i) s += red[tid * 32 + i];
        g_mv4[(size_t)unit * L_SEQ + tid] = s;
    }
}

// ---------------------------------------------------------------------------
// Phase B: combine channel-quarters, global mean over b, top-4 per v (ties ->
// lowest index, matching lax.top_k), softmax per (b,v). Tiny.
// ---------------------------------------------------------------------------
__global__ void topk_kernel() {
    const int v = blockIdx.x;
    __shared__ float gm[L_SEQ];
    __shared__ int ids[TOPK];
    const int tid = threadIdx.x;
    if (tid < L_SEQ) {
        float s = 0.f;
        for (int b = 0; b < N_B; ++b) {
            const int u = (b * N_V + v) * N_UNITS;
#pragma unroll
            for (int r = 0; r < N_UNITS; ++r)
                s += g_mv4[(size_t)(u + r) * L_SEQ + tid];
        }
        gm[tid] = s;
    }
    __syncthreads();
    if (tid == 0) {
        for (int kk = 0; kk < TOPK; ++kk) {
            float best = -3.0e38f; int bi = 0;
            for (int l = 0; l < L_SEQ; ++l)
                if (gm[l] > best) { best = gm[l]; bi = l; }
            ids[kk] = bi;
            gm[bi] = -3.0e38f;
            g_idx[v * TOPK + kk] = bi;
        }
    }
    __syncthreads();
    if (tid < N_B) {
        const int b = tid;
        const int u = (b * N_V + v) * N_UNITS;
        float w[TOPK];
        float mx = -3.0e38f;
        for (int kk = 0; kk < TOPK; ++kk) {
            const int id = ids[kk];
            float s = 0.f;
#pragma unroll
            for (int r = 0; r < N_UNITS; ++r)
                s += g_mv4[(size_t)(u + r) * L_SEQ + id];
            w[kk] = s * (1.0f / 512.0f);
            mx = fmaxf(mx, w[kk]);
        }
        float se = 0.f;
        for (int kk = 0; kk < TOPK; ++kk) { w[kk] = expf(w[kk] - mx); se += w[kk]; }
        const float inv = 1.0f / se;
        for (int kk = 0; kk < TOPK; ++kk)
            g_prob[(b * N_V + v) * TOPK + kk] = w[kk] * inv;
    }
}

// ---------------------------------------------------------------------------
// Phase C: out[b,l,v,e,h] = sum_kk p * val[b,(l+idx_kk)%96,v,h,e].
// Read-once, one CTA per (b, v, e-octant). The (h,e)->(e,h) transpose happens
// DURING staging: smem is output-major s[t*64 + co] with co = e'*8+h, so the
// compute pass is pure LDS.128 + FFMA + STG.128, all conflict-free/coalesced.
// ---------------------------------------------------------------------------
#define TPB_G 256

__global__ __launch_bounds__(TPB_G) void agg_kernel(const float* __restrict__ val,
                                                    float* __restrict__ out) {
    __shared__ float s[L_SEQ * 64];            // 24,576 B, output-major
    const int blk = blockIdx.x;
    const int bv = blk >> 3;
    const int ep = blk & 7;                    // e-octant
    const int b = bv / N_V, v = bv % N_V;
    const int e0 = ep * 8;
    const int tid = threadIdx.x;

    int idx[TOPK]; float p[TOPK];
#pragma unroll
    for (int kk = 0; kk < TOPK; ++kk) {
        idx[kk] = g_idx[v * TOPK + kk];
        p[kk]   = g_prob[(b * N_V + v) * TOPK + kk];
    }
    const size_t base = ((size_t)b * L_SEQ * N_V + v) * N_C;
    const size_t rstr = (size_t)N_V * N_C;

    // stage + transpose: 96 t x 8 h x 8 e' floats as 3072 float2 loads
#pragma unroll
    for (int it = 0; it < 3072 / TPB_G; ++it) {
        const int j = tid + it * TPB_G;
        const int t = j >> 5;
        const int r = j & 31;
        const int h = r >> 2;
        const int e2 = (r & 3) * 2;
        const float2 x = *reinterpret_cast<const float2*>(
            val + base + (size_t)t * rstr + h * 64 + e0 + e2);
        s[t * 64 + e2 * 8 + h]       = x.x;     // co = e'*8 + h
        s[t * 64 + (e2 + 1) * 8 + h] = x.y;
    }
    __syncthreads();

    const int co0 = (tid & 15) * 4;  // 4 consecutive out channels
    const int lz  = tid >> 4;        // 0..15

#pragma unroll
    for (int li = 0; li < L_SEQ / 16; ++li) {
        const int l = lz + li * 16;
        float4 r = make_float4(0.f, 0.f, 0.f, 0.f);
#pragma unroll
        for (int kk = 0; kk < TOPK; ++kk) {
            int t = l + idx[kk];
            if (t >= L_SEQ) t -= L_SEQ;
            const float4 x = *reinterpret_cast<const float4*>(&s[t * 64 + co0]);
            r.x += p[kk] * x.x; r.y += p[kk] * x.y;
            r.z += p[kk] * x.z; r.w += p[kk] * x.w;
        }
        *reinterpret_cast<float4*>(out + base + (size_t)l * rstr + e0 * 8 + co0) = r;
    }
}

extern "C" void kernel_launch(void* const* d_in, const int* in_sizes, int n_in,
                              void* d_out, int out_size) {
    const float* q  = (const float*)d_in[0];
    const float* k  = (const float*)d_in[1];
    const float* vv = (const float*)d_in[2];
    float* out = (float*)d_out;

    corr_kernel<<<N_B * N_V * N_UNITS, TPB_A>>>(q, k);
    topk_kernel<<<N_V, 128>>>();
    agg_kernel<<<N_B * N_V * 8, TPB_G>>>(vv, out);
}